// round 6
// baseline (speedup 1.0000x reference)
#include <cuda_runtime.h>
#include <math.h>

// ---------------- problem constants ----------------
#define N8   130560   // (2176/8)*(3840/8)
#define N16  32640
#define N32  8160
#define NT   (N8 + N16 + N32)   // 171360
#define N8_4  (N8 / 4)
#define N16_4 (N16 / 4)
#define N32_4 (N32 / 4)
#define NT4   (NT / 4)
#define FW8  480
#define FW16 240
#define FW32 120
#define TOPK 1000
#define NCAND 4096
#define NBINS 4096
#define NMS_T 0.4f

#define GRID 148
#define BLK  512
#define NTHREADS (GRID * BLK)      // 75776
#define NWARPS   (NTHREADS / 32)   // 2368

// ---------------- device scratch (no allocations allowed) ----------------
__device__ unsigned int        g_keys[NT];
__device__ unsigned int        g_hist[NBINS];          // zero at load; re-zeroed every run
__device__ unsigned int        g_ccount;               // zero at load; reset every run
__device__ unsigned long long  g_cand[NCAND];
__device__ float               g_bx[1024 * 4];
__device__ float               g_sc[1024];
__device__ float               g_kp[1024 * 10];
__device__ int                 g_val[1024];
__device__ unsigned int        g_mask[1024 * 32];
// software grid barrier (generation-based; survives graph replays)
__device__ unsigned int           g_bar_count;
__device__ volatile unsigned int  g_bar_gen;

__device__ __forceinline__ void grid_sync() {
    __syncthreads();
    if (threadIdx.x == 0) {
        __threadfence();
        unsigned int gen = g_bar_gen;
        if (atomicAdd(&g_bar_count, 1u) == GRID - 1) {
            g_bar_count = 0;
            __threadfence();
            g_bar_gen = gen + 1;
        } else {
            while (g_bar_gen == gen) { }
        }
        __threadfence();
    }
    __syncthreads();
}

__device__ __forceinline__ unsigned int sig_key(float raw) {
    float sg = 1.0f / (1.0f + expf(-raw));
    return (sg > 0.5f) ? __float_as_uint(sg) : 0u;
}

__device__ __forceinline__ void hist_add(unsigned int key) {
    if (key) {
        unsigned int bin = (key - 0x3F000000u) >> 11;
        if (bin > NBINS - 1) bin = NBINS - 1;
        atomicAdd(&g_hist[bin], 1u);
    }
}

__global__ __launch_bounds__(BLK)
void k_all(const float* __restrict__ s8,  const float* __restrict__ b8,  const float* __restrict__ k8,
           const float* __restrict__ s16, const float* __restrict__ b16, const float* __restrict__ k16,
           const float* __restrict__ s32, const float* __restrict__ b32, const float* __restrict__ k32,
           float* __restrict__ out) {
    const int tid  = blockIdx.x * BLK + threadIdx.x;
    const int t    = threadIdx.x;
    const int lane = t & 31;
    const int w    = t >> 5;

    // ---------- Phase A: sigmoid -> key (vectorized), histogram ----------
    // valid keys (sigmoid > 0.5) lie in (0x3F000000, 0x3F800000]; bin = mantissa[22:11]
    for (int v = tid; v < NT4; v += NTHREADS) {
        float4 r;
        if (v < N8_4)               r = reinterpret_cast<const float4*>(s8)[v];
        else if (v < N8_4 + N16_4)  r = reinterpret_cast<const float4*>(s16)[v - N8_4];
        else                        r = reinterpret_cast<const float4*>(s32)[v - N8_4 - N16_4];
        uint4 k;
        k.x = sig_key(r.x); k.y = sig_key(r.y); k.z = sig_key(r.z); k.w = sig_key(r.w);
        reinterpret_cast<uint4*>(g_keys)[v] = k;
        hist_add(k.x); hist_add(k.y); hist_add(k.z); hist_add(k.w);
    }
    grid_sync();

    // ---------- Phase B (per-block, redundant): kmin s.t. count >= TOPK ----------
    __shared__ unsigned int sw_tot[BLK / 32];
    __shared__ unsigned int skmin;
    unsigned int kmin;
    {
        unsigned int loc[8];
        unsigned int p = 0;
        #pragma unroll
        for (int b = 0; b < 8; b++) { loc[b] = g_hist[t * 8 + b]; p += loc[b]; }
        // warp suffix-sum toward higher lanes (s = sum of p over lanes >= lane)
        unsigned int s = p;
        #pragma unroll
        for (int d = 1; d < 32; d <<= 1) {
            unsigned int o = __shfl_down_sync(0xFFFFFFFFu, s, d);
            if (lane + d < 32) s += o;
        }
        unsigned int wtot = __shfl_sync(0xFFFFFFFFu, s, 0);
        if (lane == 0) sw_tot[w] = wtot;
        __syncthreads();
        unsigned int tail = 0;
        #pragma unroll
        for (int ww = 0; ww < BLK / 32; ww++) tail += (ww > w) ? sw_tot[ww] : 0u;
        unsigned int suffix = s + tail;     // sum of bins [t*8 .. NBINS)
        unsigned int nxt = suffix - p;      // sum of bins [(t+1)*8 .. NBINS)
        if (suffix >= TOPK && nxt < TOPK) {
            unsigned int running = nxt;
            int B = t * 8;
            #pragma unroll
            for (int b = 7; b >= 0; b--) {
                running += loc[b];
                if (running >= TOPK) { B = t * 8 + b; break; }
            }
            skmin = 0x3F000000u + ((unsigned int)B << 11);
        }
        if (t == 0 && suffix < TOPK) skmin = 0x3F000000u;
        __syncthreads();
        kmin = skmin;
    }

    // ---------- Phase C: collect candidates (vectorized) ----------
    for (int v = tid; v < NT4; v += NTHREADS) {
        uint4 k = reinterpret_cast<uint4*>(g_keys)[v];
        unsigned int base = (unsigned int)v * 4u;
        if (k.x >= kmin) {
            unsigned int pos = atomicAdd(&g_ccount, 1u);
            if (pos < NCAND) g_cand[pos] = ((unsigned long long)k.x << 32) | (unsigned long long)(0xFFFFFFFFu - base);
        }
        if (k.y >= kmin) {
            unsigned int pos = atomicAdd(&g_ccount, 1u);
            if (pos < NCAND) g_cand[pos] = ((unsigned long long)k.y << 32) | (unsigned long long)(0xFFFFFFFFu - (base + 1u));
        }
        if (k.z >= kmin) {
            unsigned int pos = atomicAdd(&g_ccount, 1u);
            if (pos < NCAND) g_cand[pos] = ((unsigned long long)k.z << 32) | (unsigned long long)(0xFFFFFFFFu - (base + 2u));
        }
        if (k.w >= kmin) {
            unsigned int pos = atomicAdd(&g_ccount, 1u);
            if (pos < NCAND) g_cand[pos] = ((unsigned long long)k.w << 32) | (unsigned long long)(0xFFFFFFFFu - (base + 3u));
        }
    }
    grid_sync();

    // ---------- Phase DE: warp-per-candidate rank + direct decode ----------
    {
        unsigned int C = g_ccount;
        if (C > NCAND) C = NCAND;

        // re-zero histogram for next replay (all blocks past Phase B now)
        for (int i = tid; i < NBINS; i += NTHREADS) g_hist[i] = 0;

        // zero never-written rows [C, 1024)
        if (tid >= (int)C && tid < 1024) {
            g_val[tid] = 0;
            g_sc[tid] = 0.0f;
            #pragma unroll
            for (int c = 0; c < 4; c++)  g_bx[tid * 4 + c] = 0.0f;
            #pragma unroll
            for (int c = 0; c < 10; c++) g_kp[tid * 10 + c] = 0.0f;
        }

        int gw = tid >> 5;
        for (int cand = gw; cand < (int)C; cand += NWARPS) {
            unsigned long long mine = g_cand[cand];
            int cnt = 0;
            for (int i = lane; i < (int)C; i += 32) cnt += (g_cand[i] > mine) ? 1 : 0;
            int rank = __reduce_add_sync(0xFFFFFFFFu, cnt);
            if (rank < TOPK && lane == 0) {
                unsigned int key = (unsigned int)(mine >> 32);
                int idx = (int)(0xFFFFFFFFu - (unsigned int)(mine & 0xFFFFFFFFu));
                int li, fw;
                float stride;
                const float* bb;
                const float* kp;
                if (idx < N8)            { li = idx;            stride = 8.0f;  fw = FW8;  bb = b8;  kp = k8;  }
                else if (idx < N8 + N16) { li = idx - N8;       stride = 16.0f; fw = FW16; bb = b16; kp = k16; }
                else                     { li = idx - N8 - N16; stride = 32.0f; fw = FW32; bb = b32; kp = k32; }
                float cx = (float)(li % fw) * stride;
                float cy = (float)(li / fw) * stride;
                const float* d = bb + (size_t)li * 4;
                g_bx[rank * 4 + 0] = cx - d[0] * stride;
                g_bx[rank * 4 + 1] = cy - d[1] * stride;
                g_bx[rank * 4 + 2] = cx + d[2] * stride;
                g_bx[rank * 4 + 3] = cy + d[3] * stride;
                const float* kk = kp + (size_t)li * 10;
                #pragma unroll
                for (int j = 0; j < 5; j++) {
                    g_kp[rank * 10 + 2 * j]     = kk[2 * j]     * stride + cx;
                    g_kp[rank * 10 + 2 * j + 1] = kk[2 * j + 1] * stride + cy;
                }
                g_sc[rank] = __uint_as_float(key);
                g_val[rank] = 1;
            }
        }
    }
    grid_sync();

    // ---------- Phase F: IoU suppression bitmask (32000 warp-tasks) ----------
    if (tid == 0) g_ccount = 0;   // consumed; reset for next replay
    {
        int gw = tid >> 5;
        for (int task = gw; task < TOPK * 32; task += NWARPS) {
            int i  = task >> 5;
            int wj = task & 31;
            int j  = wj * 32 + lane;
            float ix1 = g_bx[i * 4 + 0], iy1 = g_bx[i * 4 + 1];
            float ix2 = g_bx[i * 4 + 2], iy2 = g_bx[i * 4 + 3];
            float iar = (ix2 - ix1) * (iy2 - iy1);
            bool bit = false;
            if (j < TOPK && j > i) {
                float jx1 = g_bx[j * 4 + 0], jy1 = g_bx[j * 4 + 1];
                float jx2 = g_bx[j * 4 + 2], jy2 = g_bx[j * 4 + 3];
                float jar = (jx2 - jx1) * (jy2 - jy1);
                float ww = fmaxf(fminf(ix2, jx2) - fmaxf(ix1, jx1), 0.0f);
                float hh = fmaxf(fminf(iy2, jy2) - fmaxf(iy1, jy1), 0.0f);
                float inter = ww * hh;
                float uni = fmaxf(iar + jar - inter, 1e-9f);
                bit = inter > NMS_T * uni;
            }
            unsigned int b = __ballot_sync(0xFFFFFFFFu, bit);
            if (lane == 0) g_mask[i * 32 + wj] = b;
        }
    }
    grid_sync();

    // ---------- Phase G: greedy bit-reduce (1 warp) + outputs ----------
    if (blockIdx.x == 0) {
        __shared__ unsigned int svalid[32];
        __shared__ unsigned int srem[32];
        for (int c = w; c < 32; c += BLK / 32) {
            int idx = c * 32 + lane;
            int v = (idx < TOPK) ? g_val[idx] : 0;
            unsigned int b = __ballot_sync(0xFFFFFFFFu, v != 0);
            if (lane == 0) svalid[c] = b;
        }
        __syncthreads();

        if (t < 32) {
            unsigned int rem = 0;
            unsigned int mA[32], mB[32];
            #pragma unroll
            for (int k = 0; k < 32; k++) mA[k] = g_mask[k * 32 + lane];

            for (int c = 0; c < 32; c += 2) {
                #pragma unroll
                for (int k = 0; k < 32; k++) mB[k] = g_mask[((c + 1) * 32 + k) * 32 + lane];
                {   // chunk c with mA
                    unsigned int vb = svalid[c];
                    unsigned int myrem = rem;
                    unsigned int kb = 0;
                    #pragma unroll
                    for (int k2 = 0; k2 < 32; k2++) {
                        unsigned int kept = ((vb >> k2) & 1u) & ((~(myrem >> k2)) & 1u);
                        kb |= kept << k2;
                        myrem |= (0u - kept) & mA[k2];
                    }
                    unsigned int keptbits = __shfl_sync(0xFFFFFFFFu, kb, c);
                    #pragma unroll
                    for (int k2 = 0; k2 < 32; k2++)
                        rem |= (0u - ((keptbits >> k2) & 1u)) & mA[k2];
                }
                if (c + 2 < 32) {
                    #pragma unroll
                    for (int k = 0; k < 32; k++) mA[k] = g_mask[((c + 2) * 32 + k) * 32 + lane];
                }
                {   // chunk c+1 with mB
                    unsigned int vb = svalid[c + 1];
                    unsigned int myrem = rem;
                    unsigned int kb = 0;
                    #pragma unroll
                    for (int k2 = 0; k2 < 32; k2++) {
                        unsigned int kept = ((vb >> k2) & 1u) & ((~(myrem >> k2)) & 1u);
                        kb |= kept << k2;
                        myrem |= (0u - kept) & mB[k2];
                    }
                    unsigned int keptbits = __shfl_sync(0xFFFFFFFFu, kb, c + 1);
                    #pragma unroll
                    for (int k2 = 0; k2 < 32; k2++)
                        rem |= (0u - ((keptbits >> k2) & 1u)) & mB[k2];
                }
            }
            srem[lane] = rem;
        }
        __syncthreads();

        // outputs: [boxes 1000*4 | scores 1000 | kpss 1000*10] = 15000 floats
        for (int r = t; r < TOPK; r += BLK) {
            unsigned int rw = srem[r >> 5];
            int keep = g_val[r] && !((rw >> (r & 31)) & 1u);
            float m = keep ? 1.0f : 0.0f;
            out[r * 4 + 0] = m * g_bx[r * 4 + 0];
            out[r * 4 + 1] = m * g_bx[r * 4 + 1];
            out[r * 4 + 2] = m * g_bx[r * 4 + 2];
            out[r * 4 + 3] = m * g_bx[r * 4 + 3];
            out[4000 + r] = m * g_sc[r];
            #pragma unroll
            for (int c = 0; c < 10; c++)
                out[5000 + r * 10 + c] = m * g_kp[r * 10 + c];
        }
    }
}

// ---------------- launcher: ONE persistent kernel ----------------
extern "C" void kernel_launch(void* const* d_in, const int* in_sizes, int n_in,
                              void* d_out, int out_size) {
    // metadata order: x, scores8, bbox8, kps8, scores16, bbox16, kps16, scores32, bbox32, kps32
    const float* s8  = (const float*)d_in[1];
    const float* b8  = (const float*)d_in[2];
    const float* k8  = (const float*)d_in[3];
    const float* s16 = (const float*)d_in[4];
    const float* b16 = (const float*)d_in[5];
    const float* k16 = (const float*)d_in[6];
    const float* s32 = (const float*)d_in[7];
    const float* b32 = (const float*)d_in[8];
    const float* k32 = (const float*)d_in[9];
    float* out = (float*)d_out;

    k_all<<<GRID, BLK>>>(s8, b8, k8, s16, b16, k16, s32, b32, k32, out);
}

// round 7
// speedup vs baseline: 2.2438x; 2.2438x over previous
#include <cuda_runtime.h>
#include <math.h>

// ---------------- problem constants ----------------
#define N8   130560   // (2176/8)*(3840/8)
#define N16  32640
#define N32  8160
#define NT   (N8 + N16 + N32)   // 171360
#define N8_4  (N8 / 4)
#define N16_4 (N16 / 4)
#define NT4   (NT / 4)
#define FW8  480
#define FW16 240
#define FW32 120
#define TOPK 1000
#define NCAND 4096
#define NBINS 4096
#define BINCAP 512
#define BINSH  9
#define NMS_T 0.4f

#define GRID 148
#define BLK  512
#define NTHREADS (GRID * BLK)      // 75776
#define NWARPS   (NTHREADS / 32)   // 2368

// ---------------- device scratch (no allocations allowed) ----------------
__device__ unsigned int        g_bincnt[NBINS];        // zero at load; re-zeroed every run
__device__ unsigned long long  g_bin[NBINS * BINCAP];  // 16 MB bucket store
__device__ unsigned int        g_ccount;               // zero at load; reset every run
__device__ unsigned long long  g_cand[NCAND];
__device__ float4              g_bx4[1024];
__device__ float               g_sc[1024];
__device__ float               g_kp[1024 * 10];
__device__ int                 g_val[1024];
__device__ unsigned int        g_mask[1024 * 32];
__device__ unsigned int        g_nzchunks;             // bit c = chunk c has nonzero mask
// software grid barrier (generation-based; survives graph replays)
__device__ unsigned int           g_bar_count;
__device__ volatile unsigned int  g_bar_gen;

__device__ __forceinline__ void grid_sync() {
    __syncthreads();
    if (threadIdx.x == 0) {
        __threadfence();
        unsigned int gen = g_bar_gen;
        if (atomicAdd(&g_bar_count, 1u) == GRID - 1) {
            g_bar_count = 0;
            __threadfence();
            g_bar_gen = gen + 1;
        } else {
            while (g_bar_gen == gen) { }
        }
        __threadfence();
    }
    __syncthreads();
}

__device__ __forceinline__ unsigned int sig_key(float raw) {
    float sg = 1.0f / (1.0f + expf(-raw));
    return (sg > 0.5f) ? __float_as_uint(sg) : 0u;
}

__device__ __forceinline__ void bin_put(unsigned int key, unsigned int idx) {
    if (key) {
        unsigned int bin = (key - 0x3F000000u) >> 11;   // < 4096 by construction
        unsigned int pos = atomicAdd(&g_bincnt[bin], 1u);
        if (pos < BINCAP)
            g_bin[(bin << BINSH) + pos] =
                ((unsigned long long)key << 32) | (unsigned long long)(0xFFFFFFFFu - idx);
    }
}

// ================= K1: sigmoid -> binned candidates =================
__global__ __launch_bounds__(BLK)
void k_front(const float* __restrict__ s8, const float* __restrict__ s16,
             const float* __restrict__ s32) {
    const int tid = blockIdx.x * BLK + threadIdx.x;
    for (int v = tid; v < NT4; v += NTHREADS) {
        float4 r;
        if (v < N8_4)               r = reinterpret_cast<const float4*>(s8)[v];
        else if (v < N8_4 + N16_4)  r = reinterpret_cast<const float4*>(s16)[v - N8_4];
        else                        r = reinterpret_cast<const float4*>(s32)[v - N8_4 - N16_4];
        unsigned int base = (unsigned int)v * 4u;
        bin_put(sig_key(r.x), base);
        bin_put(sig_key(r.y), base + 1u);
        bin_put(sig_key(r.z), base + 2u);
        bin_put(sig_key(r.w), base + 3u);
    }
}

// ========== K2: boundary bin -> gather -> rank-sort -> decode ==========
__global__ __launch_bounds__(BLK)
void k_mid(const float* __restrict__ b8,  const float* __restrict__ k8,
           const float* __restrict__ b16, const float* __restrict__ k16,
           const float* __restrict__ b32, const float* __restrict__ k32) {
    const int tid  = blockIdx.x * BLK + threadIdx.x;
    const int t    = threadIdx.x;
    const int lane = t & 31;
    const int w    = t >> 5;

    // ---- B: per-block redundant boundary-bin search ----
    __shared__ unsigned int sw_tot[BLK / 32];
    __shared__ int sBidx;
    int Bidx;
    {
        unsigned int loc[8];
        unsigned int p = 0;
        #pragma unroll
        for (int b = 0; b < 8; b++) { loc[b] = g_bincnt[t * 8 + b]; p += loc[b]; }
        unsigned int s = p;   // warp suffix-sum (lanes >= lane)
        #pragma unroll
        for (int d = 1; d < 32; d <<= 1) {
            unsigned int o = __shfl_down_sync(0xFFFFFFFFu, s, d);
            if (lane + d < 32) s += o;
        }
        unsigned int wtot = __shfl_sync(0xFFFFFFFFu, s, 0);
        if (lane == 0) sw_tot[w] = wtot;
        __syncthreads();
        unsigned int tail = 0;
        #pragma unroll
        for (int ww = 0; ww < BLK / 32; ww++) tail += (ww > w) ? sw_tot[ww] : 0u;
        unsigned int suffix = s + tail;     // sum of bins [t*8 .. NBINS)
        unsigned int nxt = suffix - p;
        if (suffix >= TOPK && nxt < TOPK) {
            unsigned int running = nxt;
            int B = t * 8;
            #pragma unroll
            for (int b = 7; b >= 0; b--) {
                running += loc[b];
                if (running >= TOPK) { B = t * 8 + b; break; }
            }
            sBidx = B;
        }
        if (t == 0 && suffix < TOPK) sBidx = 0;
        __syncthreads();
        Bidx = sBidx;
    }

    // ---- C': gather candidates from suffix bins ----
    for (int b = Bidx + tid; b < NBINS; b += NTHREADS) {
        unsigned int n = g_bincnt[b];
        if (n > BINCAP) n = BINCAP;
        if (n) {
            unsigned int base = atomicAdd(&g_ccount, n);
            for (unsigned int e = 0; e < n && base + e < NCAND; e++)
                g_cand[base + e] = g_bin[(b << BINSH) + e];
        }
    }
    grid_sync();

    // ---- DE: warp-per-candidate rank + direct decode ----
    unsigned int C = g_ccount;
    if (C > NCAND) C = NCAND;

    // re-zero bins for next replay; clear nz bitmap
    for (int i = tid; i < NBINS; i += NTHREADS) g_bincnt[i] = 0;
    if (tid == 0) g_nzchunks = 0u;

    // zero never-written rank rows [C, 1024)
    if (tid >= (int)C && tid < 1024) {
        g_val[tid] = 0;
        g_sc[tid] = 0.0f;
        g_bx4[tid] = make_float4(0.0f, 0.0f, 0.0f, 0.0f);
        #pragma unroll
        for (int c = 0; c < 10; c++) g_kp[tid * 10 + c] = 0.0f;
    }

    int gw = tid >> 5;
    for (int cand = gw; cand < (int)C; cand += NWARPS) {
        unsigned long long mine = g_cand[cand];
        int cnt = 0;
        for (int i = lane; i < (int)C; i += 32) cnt += (g_cand[i] > mine) ? 1 : 0;
        int rank = __reduce_add_sync(0xFFFFFFFFu, cnt);
        if (rank < TOPK && lane == 0) {
            unsigned int key = (unsigned int)(mine >> 32);
            int idx = (int)(0xFFFFFFFFu - (unsigned int)(mine & 0xFFFFFFFFu));
            int li, fw;
            float stride;
            const float* bb;
            const float* kp;
            if (idx < N8)            { li = idx;            stride = 8.0f;  fw = FW8;  bb = b8;  kp = k8;  }
            else if (idx < N8 + N16) { li = idx - N8;       stride = 16.0f; fw = FW16; bb = b16; kp = k16; }
            else                     { li = idx - N8 - N16; stride = 32.0f; fw = FW32; bb = b32; kp = k32; }
            float cx = (float)(li % fw) * stride;
            float cy = (float)(li / fw) * stride;
            const float* d = bb + (size_t)li * 4;
            g_bx4[rank] = make_float4(cx - d[0] * stride, cy - d[1] * stride,
                                      cx + d[2] * stride, cy + d[3] * stride);
            const float* kk = kp + (size_t)li * 10;
            #pragma unroll
            for (int j = 0; j < 5; j++) {
                g_kp[rank * 10 + 2 * j]     = kk[2 * j]     * stride + cx;
                g_kp[rank * 10 + 2 * j + 1] = kk[2 * j + 1] * stride + cy;
            }
            g_sc[rank] = __uint_as_float(key);
            g_val[rank] = 1;
        }
    }
}

// ========== K3: IoU mask -> sparse greedy reduce -> outputs ==========
__global__ __launch_bounds__(BLK)
void k_back(float* __restrict__ out) {
    const int tid  = blockIdx.x * BLK + threadIdx.x;
    const int t    = threadIdx.x;
    const int lane = t & 31;
    const int w    = t >> 5;

    if (tid == 0) g_ccount = 0;   // consumed in k_mid; reset for next replay

    // ---- F: suppression bitmask, float4 loads, nz-chunk bitmap ----
    {
        int gw = tid >> 5;
        for (int task = gw; task < TOPK * 32; task += NWARPS) {
            int i  = task >> 5;
            int wj = task & 31;
            if (wj * 32 + 31 <= i) {            // whole word is j <= i: zero
                if (lane == 0) g_mask[i * 32 + wj] = 0u;
                continue;
            }
            float4 bi = g_bx4[i];
            int j = wj * 32 + lane;
            float4 bj = g_bx4[j];
            bool bit = false;
            if (j < TOPK && j > i) {
                float iar = (bi.z - bi.x) * (bi.w - bi.y);
                float jar = (bj.z - bj.x) * (bj.w - bj.y);
                float ww2 = fmaxf(fminf(bi.z, bj.z) - fmaxf(bi.x, bj.x), 0.0f);
                float hh2 = fmaxf(fminf(bi.w, bj.w) - fmaxf(bi.y, bj.y), 0.0f);
                float inter = ww2 * hh2;
                float uni = fmaxf(iar + jar - inter, 1e-9f);
                bit = inter > NMS_T * uni;
            }
            unsigned int b = __ballot_sync(0xFFFFFFFFu, bit);
            if (lane == 0) {
                g_mask[i * 32 + wj] = b;
                if (b) atomicOr(&g_nzchunks, 1u << (i >> 5));
            }
        }
    }
    grid_sync();

    // ---- G: greedy reduce over nonzero chunks only + outputs ----
    if (blockIdx.x == 0) {
        __shared__ unsigned int svalid[32];
        __shared__ unsigned int srem[32];
        for (int c = w; c < 32; c += BLK / 32) {
            int idx = c * 32 + lane;
            int v = (idx < TOPK) ? g_val[idx] : 0;
            unsigned int b = __ballot_sync(0xFFFFFFFFu, v != 0);
            if (lane == 0) svalid[c] = b;
        }
        __syncthreads();

        if (t < 32) {
            unsigned int rem = 0;
            unsigned int nz = g_nzchunks;    // uniform across lanes
            while (nz) {
                int c = __ffs(nz) - 1;       // ascending chunk order (greedy order)
                nz &= nz - 1;
                unsigned int m[32];
                #pragma unroll
                for (int k = 0; k < 32; k++) m[k] = g_mask[(c * 32 + k) * 32 + lane];
                unsigned int vb = svalid[c];
                unsigned int myrem = rem;
                unsigned int kb = 0;
                #pragma unroll
                for (int k2 = 0; k2 < 32; k2++) {
                    unsigned int kept = ((vb >> k2) & 1u) & ((~(myrem >> k2)) & 1u);
                    kb |= kept << k2;
                    myrem |= (0u - kept) & m[k2];
                }
                unsigned int keptbits = __shfl_sync(0xFFFFFFFFu, kb, c);
                #pragma unroll
                for (int k2 = 0; k2 < 32; k2++)
                    rem |= (0u - ((keptbits >> k2) & 1u)) & m[k2];
            }
            srem[lane] = rem;
        }
        __syncthreads();

        // outputs: [boxes 1000*4 | scores 1000 | kpss 1000*10] = 15000 floats
        for (int r = t; r < TOPK; r += BLK) {
            unsigned int rw = srem[r >> 5];
            int keep = g_val[r] && !((rw >> (r & 31)) & 1u);
            float m = keep ? 1.0f : 0.0f;
            float4 b = g_bx4[r];
            out[r * 4 + 0] = m * b.x;
            out[r * 4 + 1] = m * b.y;
            out[r * 4 + 2] = m * b.z;
            out[r * 4 + 3] = m * b.w;
            out[4000 + r] = m * g_sc[r];
            #pragma unroll
            for (int c = 0; c < 10; c++)
                out[5000 + r * 10 + c] = m * g_kp[r * 10 + c];
        }
    }
}

// ---------------- launcher: 3 graph nodes ----------------
extern "C" void kernel_launch(void* const* d_in, const int* in_sizes, int n_in,
                              void* d_out, int out_size) {
    // metadata order: x, scores8, bbox8, kps8, scores16, bbox16, kps16, scores32, bbox32, kps32
    const float* s8  = (const float*)d_in[1];
    const float* b8  = (const float*)d_in[2];
    const float* k8  = (const float*)d_in[3];
    const float* s16 = (const float*)d_in[4];
    const float* b16 = (const float*)d_in[5];
    const float* k16 = (const float*)d_in[6];
    const float* s32 = (const float*)d_in[7];
    const float* b32 = (const float*)d_in[8];
    const float* k32 = (const float*)d_in[9];
    float* out = (float*)d_out;

    k_front<<<GRID, BLK>>>(s8, s16, s32);
    k_mid<<<GRID, BLK>>>(b8, k8, b16, k16, b32, k32);
    k_back<<<GRID, BLK>>>(out);
}

// round 9
// speedup vs baseline: 2.3359x; 1.0410x over previous
#include <cuda_runtime.h>
#include <math.h>

// ---------------- problem constants ----------------
#define N8   130560   // (2176/8)*(3840/8)
#define N16  32640
#define N32  8160
#define NT   (N8 + N16 + N32)   // 171360
#define N8_4  (N8 / 4)
#define N16_4 (N16 / 4)
#define NT4   (NT / 4)
#define FW8  480
#define FW16 240
#define FW32 120
#define TOPK 1000
#define NCAND 4096
#define NBINS 4096
#define NMS_T 0.4f

#define GRID 148
#define BLK  512
#define NTHREADS (GRID * BLK)      // 75776
#define NWARPS   (NTHREADS / 32)   // 2368

// ---------------- device scratch (no allocations allowed) ----------------
__device__ unsigned int        g_hist[NBINS];          // zero at load; re-zeroed every run
__device__ unsigned int        g_ccount;               // zero at load; reset every run
__device__ unsigned long long  g_cand[NCAND];
__device__ float4              g_bx4[1024];
__device__ float               g_sc[1024];
__device__ float               g_kp[1024 * 10];
__device__ int                 g_val[1024];
__device__ unsigned int        g_mask[1024 * 32];
__device__ unsigned int        g_nzchunks;             // bit c = chunk c has nonzero mask
// software grid barrier (generation-based; survives graph replays)
__device__ unsigned int           g_bar_count;
__device__ volatile unsigned int  g_bar_gen;

__device__ __forceinline__ void grid_sync() {
    __syncthreads();
    if (threadIdx.x == 0) {
        __threadfence();
        unsigned int gen = g_bar_gen;
        if (atomicAdd(&g_bar_count, 1u) == GRID - 1) {
            g_bar_count = 0;
            __threadfence();
            g_bar_gen = gen + 1;
        } else {
            while (g_bar_gen == gen) { }
        }
        __threadfence();
    }
    __syncthreads();
}

__device__ __forceinline__ unsigned int sig_key(float raw) {
    float sg = 1.0f / (1.0f + expf(-raw));
    return (sg > 0.5f) ? __float_as_uint(sg) : 0u;
}

__device__ __forceinline__ void hist_add(unsigned int key) {
    if (key) {
        unsigned int bin = (key - 0x3F000000u) >> 11;   // < 4096 by construction
        atomicAdd(&g_hist[bin], 1u);
    }
}

// ================= K1: sigmoid -> histogram only =================
__global__ __launch_bounds__(BLK)
void k_front(const float* __restrict__ s8, const float* __restrict__ s16,
             const float* __restrict__ s32) {
    const int tid = blockIdx.x * BLK + threadIdx.x;
    for (int v = tid; v < NT4; v += NTHREADS) {
        float4 r;
        if (v < N8_4)               r = reinterpret_cast<const float4*>(s8)[v];
        else if (v < N8_4 + N16_4)  r = reinterpret_cast<const float4*>(s16)[v - N8_4];
        else                        r = reinterpret_cast<const float4*>(s32)[v - N8_4 - N16_4];
        hist_add(sig_key(r.x));
        hist_add(sig_key(r.y));
        hist_add(sig_key(r.z));
        hist_add(sig_key(r.w));
    }
}

// ===== K2: kmin -> rescan-collect -> rank+decode -> mask -> reduce -> out =====
__global__ __launch_bounds__(BLK)
void k_rest(const float* __restrict__ s8,  const float* __restrict__ s16, const float* __restrict__ s32,
            const float* __restrict__ b8,  const float* __restrict__ k8,
            const float* __restrict__ b16, const float* __restrict__ k16,
            const float* __restrict__ b32, const float* __restrict__ k32,
            float* __restrict__ out) {
    const int tid  = blockIdx.x * BLK + threadIdx.x;
    const int t    = threadIdx.x;
    const int lane = t & 31;
    const int w    = t >> 5;

    // ---- B: per-block redundant boundary-bin search ----
    __shared__ unsigned int sw_tot[BLK / 32];
    __shared__ unsigned int skmin;
    unsigned int kmin;
    {
        unsigned int loc[8];
        unsigned int p = 0;
        #pragma unroll
        for (int b = 0; b < 8; b++) { loc[b] = g_hist[t * 8 + b]; p += loc[b]; }
        unsigned int s = p;   // warp suffix-sum (lanes >= lane)
        #pragma unroll
        for (int d = 1; d < 32; d <<= 1) {
            unsigned int o = __shfl_down_sync(0xFFFFFFFFu, s, d);
            if (lane + d < 32) s += o;
        }
        unsigned int wtot = __shfl_sync(0xFFFFFFFFu, s, 0);
        if (lane == 0) sw_tot[w] = wtot;
        __syncthreads();
        unsigned int tail = 0;
        #pragma unroll
        for (int ww = 0; ww < BLK / 32; ww++) tail += (ww > w) ? sw_tot[ww] : 0u;
        unsigned int suffix = s + tail;     // sum of bins [t*8 .. NBINS)
        unsigned int nxt = suffix - p;
        if (suffix >= TOPK && nxt < TOPK) {
            unsigned int running = nxt;
            int B = t * 8;
            #pragma unroll
            for (int b = 7; b >= 0; b--) {
                running += loc[b];
                if (running >= TOPK) { B = t * 8 + b; break; }
            }
            skmin = 0x3F000000u + ((unsigned int)B << 11);
        }
        if (t == 0 && suffix < TOPK) skmin = 0x3F000000u;
        __syncthreads();
        kmin = skmin;
    }

    // ---- C: rescan scores, collect candidates >= kmin ----
    for (int v = tid; v < NT4; v += NTHREADS) {
        float4 r;
        if (v < N8_4)               r = reinterpret_cast<const float4*>(s8)[v];
        else if (v < N8_4 + N16_4)  r = reinterpret_cast<const float4*>(s16)[v - N8_4];
        else                        r = reinterpret_cast<const float4*>(s32)[v - N8_4 - N16_4];
        unsigned int k0 = sig_key(r.x), k1 = sig_key(r.y), k2 = sig_key(r.z), k3 = sig_key(r.w);
        unsigned int base = (unsigned int)v * 4u;
        if (k0 >= kmin) {
            unsigned int pos = atomicAdd(&g_ccount, 1u);
            if (pos < NCAND) g_cand[pos] = ((unsigned long long)k0 << 32) | (unsigned long long)(0xFFFFFFFFu - base);
        }
        if (k1 >= kmin) {
            unsigned int pos = atomicAdd(&g_ccount, 1u);
            if (pos < NCAND) g_cand[pos] = ((unsigned long long)k1 << 32) | (unsigned long long)(0xFFFFFFFFu - (base + 1u));
        }
        if (k2 >= kmin) {
            unsigned int pos = atomicAdd(&g_ccount, 1u);
            if (pos < NCAND) g_cand[pos] = ((unsigned long long)k2 << 32) | (unsigned long long)(0xFFFFFFFFu - (base + 2u));
        }
        if (k3 >= kmin) {
            unsigned int pos = atomicAdd(&g_ccount, 1u);
            if (pos < NCAND) g_cand[pos] = ((unsigned long long)k3 << 32) | (unsigned long long)(0xFFFFFFFFu - (base + 3u));
        }
    }
    grid_sync();

    // ---- DE: warp-per-candidate rank + direct decode ----
    {
        unsigned int C = g_ccount;
        if (C > NCAND) C = NCAND;

        // re-zero histogram for next replay; clear nz bitmap
        for (int i = tid; i < NBINS; i += NTHREADS) g_hist[i] = 0;
        if (tid == 0) g_nzchunks = 0u;

        // zero never-written rank rows [C, 1024)
        if (tid >= (int)C && tid < 1024) {
            g_val[tid] = 0;
            g_sc[tid] = 0.0f;
            g_bx4[tid] = make_float4(0.0f, 0.0f, 0.0f, 0.0f);
            #pragma unroll
            for (int c = 0; c < 10; c++) g_kp[tid * 10 + c] = 0.0f;
        }

        int gw = tid >> 5;
        for (int cand = gw; cand < (int)C; cand += NWARPS) {
            unsigned long long mine = g_cand[cand];
            int cnt = 0;
            for (int i = lane; i < (int)C; i += 32) cnt += (g_cand[i] > mine) ? 1 : 0;
            int rank = __reduce_add_sync(0xFFFFFFFFu, cnt);
            if (rank < TOPK && lane == 0) {
                unsigned int key = (unsigned int)(mine >> 32);
                int idx = (int)(0xFFFFFFFFu - (unsigned int)(mine & 0xFFFFFFFFu));
                int li, fw;
                float stride;
                const float* bb;
                const float* kp;
                if (idx < N8)            { li = idx;            stride = 8.0f;  fw = FW8;  bb = b8;  kp = k8;  }
                else if (idx < N8 + N16) { li = idx - N8;       stride = 16.0f; fw = FW16; bb = b16; kp = k16; }
                else                     { li = idx - N8 - N16; stride = 32.0f; fw = FW32; bb = b32; kp = k32; }
                float cx = (float)(li % fw) * stride;
                float cy = (float)(li / fw) * stride;
                const float* d = bb + (size_t)li * 4;
                g_bx4[rank] = make_float4(cx - d[0] * stride, cy - d[1] * stride,
                                          cx + d[2] * stride, cy + d[3] * stride);
                const float* kk = kp + (size_t)li * 10;
                #pragma unroll
                for (int j = 0; j < 5; j++) {
                    g_kp[rank * 10 + 2 * j]     = kk[2 * j]     * stride + cx;
                    g_kp[rank * 10 + 2 * j + 1] = kk[2 * j + 1] * stride + cy;
                }
                g_sc[rank] = __uint_as_float(key);
                g_val[rank] = 1;
            }
        }
    }
    grid_sync();

    // ---- F: suppression bitmask, float4 loads, nz-chunk bitmap ----
    if (tid == 0) g_ccount = 0;   // consumed; reset for next replay
    {
        int gw = tid >> 5;
        for (int task = gw; task < TOPK * 32; task += NWARPS) {
            int i  = task >> 5;
            int wj = task & 31;
            if (wj * 32 + 31 <= i) {            // whole word is j <= i: zero
                if (lane == 0) g_mask[i * 32 + wj] = 0u;
                continue;
            }
            float4 bi = g_bx4[i];
            int j = wj * 32 + lane;
            float4 bj = g_bx4[j];
            bool bit = false;
            if (j < TOPK && j > i) {
                float iar = (bi.z - bi.x) * (bi.w - bi.y);
                float jar = (bj.z - bj.x) * (bj.w - bj.y);
                float ww2 = fmaxf(fminf(bi.z, bj.z) - fmaxf(bi.x, bj.x), 0.0f);
                float hh2 = fmaxf(fminf(bi.w, bj.w) - fmaxf(bi.y, bj.y), 0.0f);
                float inter = ww2 * hh2;
                float uni = fmaxf(iar + jar - inter, 1e-9f);
                bit = inter > NMS_T * uni;
            }
            unsigned int b = __ballot_sync(0xFFFFFFFFu, bit);
            if (lane == 0) {
                g_mask[i * 32 + wj] = b;
                if (b) atomicOr(&g_nzchunks, 1u << (i >> 5));
            }
        }
    }
    grid_sync();

    // ---- G: greedy reduce over nonzero chunks only + outputs ----
    if (blockIdx.x == 0) {
        __shared__ unsigned int svalid[32];
        __shared__ unsigned int srem[32];
        for (int c = w; c < 32; c += BLK / 32) {
            int idx = c * 32 + lane;
            int v = (idx < TOPK) ? g_val[idx] : 0;
            unsigned int b = __ballot_sync(0xFFFFFFFFu, v != 0);
            if (lane == 0) svalid[c] = b;
        }
        __syncthreads();

        if (t < 32) {
            unsigned int rem = 0;
            unsigned int nz = g_nzchunks;    // uniform across lanes
            while (nz) {
                int c = __ffs(nz) - 1;       // ascending chunk order (greedy order)
                nz &= nz - 1;
                unsigned int m[32];
                #pragma unroll
                for (int k = 0; k < 32; k++) m[k] = g_mask[(c * 32 + k) * 32 + lane];
                unsigned int vb = svalid[c];
                unsigned int myrem = rem;
                unsigned int kb = 0;
                #pragma unroll
                for (int k2 = 0; k2 < 32; k2++) {
                    unsigned int kept = ((vb >> k2) & 1u) & ((~(myrem >> k2)) & 1u);
                    kb |= kept << k2;
                    myrem |= (0u - kept) & m[k2];
                }
                unsigned int keptbits = __shfl_sync(0xFFFFFFFFu, kb, c);
                #pragma unroll
                for (int k2 = 0; k2 < 32; k2++)
                    rem |= (0u - ((keptbits >> k2) & 1u)) & m[k2];
            }
            srem[lane] = rem;
        }
        __syncthreads();

        // outputs: [boxes 1000*4 | scores 1000 | kpss 1000*10] = 15000 floats
        for (int r = t; r < TOPK; r += BLK) {
            unsigned int rw = srem[r >> 5];
            int keep = g_val[r] && !((rw >> (r & 31)) & 1u);
            float m = keep ? 1.0f : 0.0f;
            float4 b = g_bx4[r];
            out[r * 4 + 0] = m * b.x;
            out[r * 4 + 1] = m * b.y;
            out[r * 4 + 2] = m * b.z;
            out[r * 4 + 3] = m * b.w;
            out[4000 + r] = m * g_sc[r];
            #pragma unroll
            for (int c = 0; c < 10; c++)
                out[5000 + r * 10 + c] = m * g_kp[r * 10 + c];
        }
    }
}

// ---------------- launcher: 2 graph nodes ----------------
extern "C" void kernel_launch(void* const* d_in, const int* in_sizes, int n_in,
                              void* d_out, int out_size) {
    // metadata order: x, scores8, bbox8, kps8, scores16, bbox16, kps16, scores32, bbox32, kps32
    const float* s8  = (const float*)d_in[1];
    const float* b8  = (const float*)d_in[2];
    const float* k8  = (const float*)d_in[3];
    const float* s16 = (const float*)d_in[4];
    const float* b16 = (const float*)d_in[5];
    const float* k16 = (const float*)d_in[6];
    const float* s32 = (const float*)d_in[7];
    const float* b32 = (const float*)d_in[8];
    const float* k32 = (const float*)d_in[9];
    float* out = (float*)d_out;

    k_front<<<GRID, BLK>>>(s8, s16, s32);
    k_rest<<<GRID, BLK>>>(s8, s16, s32, b8, k8, b16, k16, b32, k32, out);
}